// round 11
// baseline (speedup 1.0000x reference)
#include <cuda_runtime.h>
#include <cuda_bf16.h>
#include <cstdint>

#define BATCH     8192
#define NCLASSES  8192
#define NGROUPS   512
#define PAD       128            // u16 slots per group (>= max group size, pad mult of 4)

// smem float-index layout for k_main
#define ROWB      8224           // row1 base: byte 32896 (128B aligned for TMA), bank shift 0
#define SMEM_FLOATS 16448        // row0[8192] | sent | pad | row1[8192] | sent | pad  (65792 B)

// Scratch: __device__ globals only (allocation is forbidden).
__device__ unsigned short g_perm_pad[NGROUPS * PAD]; // per-group columns (stable), sentinel = 8192
__device__ int            g_iters[NGROUPS];          // ceil(cnt/4) uint2 iterations per group

// ---------------------------------------------------------------------------
// K1: build padded, stable per-group column lists. 64 blocks x 256 threads;
// block stages seg (32KB int4) to smem, 8 warps own one group each.
// Vectorized scan: 4 columns per lane per iteration (64 iters, not 256).
// Rank within a 128-col chunk for lane L, sub k: all matches of lanes < L
// (any k') + own lane's matches with k' < k  ->  S + prefix(b0..b2).
// ---------------------------------------------------------------------------
__global__ __launch_bounds__(256)
void k_perm(const int* __restrict__ seg) {
    __shared__ int4 sseg4[NCLASSES / 4];
    const int t = threadIdx.x;

    const int4* s4 = (const int4*)seg;
    #pragma unroll
    for (int k = 0; k < 8; ++k)
        sseg4[t + k * 256] = s4[t + k * 256];
    __syncthreads();

    const int      lane = t & 31;
    const int      g    = blockIdx.x * 8 + (t >> 5);
    const unsigned lm   = (1u << lane) - 1u;
    unsigned short* dst = g_perm_pad + g * PAD;

    int cnt = 0;
    #pragma unroll 4
    for (int i = 0; i < 64; ++i) {
        const int4 v = sseg4[i * 32 + lane];
        const unsigned m0 = __ballot_sync(0xffffffffu, v.x == g);
        const unsigned m1 = __ballot_sync(0xffffffffu, v.y == g);
        const unsigned m2 = __ballot_sync(0xffffffffu, v.z == g);
        const unsigned m3 = __ballot_sync(0xffffffffu, v.w == g);
        const int base = (i * 32 + lane) * 4;
        const int S = __popc(m0 & lm) + __popc(m1 & lm)
                    + __popc(m2 & lm) + __popc(m3 & lm);
        const int b0 = (v.x == g), b1 = (v.y == g), b2 = (v.z == g);
        if (v.x == g) dst[cnt + S]                = (unsigned short)(base);
        if (v.y == g) dst[cnt + S + b0]           = (unsigned short)(base + 1);
        if (v.z == g) dst[cnt + S + b0 + b1]      = (unsigned short)(base + 2);
        if (v.w == g) dst[cnt + S + b0 + b1 + b2] = (unsigned short)(base + 3);
        cnt += __popc(m0) + __popc(m1) + __popc(m2) + __popc(m3);
    }
    for (int j = cnt + lane; j < PAD; j += 32)           // sentinel fill
        dst[j] = (unsigned short)NCLASSES;
    if (lane == 0) g_iters[g] = (cnt + 3) >> 2;          // uint2 (4-col) iterations
}

// ---------------------------------------------------------------------------
// K2: hot kernel. Two 32KB rows staged by cp.async.bulk with SEPARATE
// mbarriers: gather of row0 starts as soon as its copy lands, overlapping
// row1's copy. Thread g gathers its group's columns (uint2 index loads,
// 4 accumulator chains), coalesced per-row output.
// ---------------------------------------------------------------------------
__global__ __launch_bounds__(512, 3)
void k_main(const float* __restrict__ x, float* __restrict__ out) {
    extern __shared__ float srow[];                  // [0,8192) row0, [8224,16416) row1
    __shared__ __align__(16) unsigned long long mbar[2];

    const int t = threadIdx.x;
    const size_t row0 = (size_t)blockIdx.x * 2;

    unsigned mbar_a, srow_a;
    asm("{ .reg .u64 a; cvta.to.shared.u64 a, %1; cvt.u32.u64 %0, a; }"
        : "=r"(mbar_a) : "l"(&mbar[0]));
    asm("{ .reg .u64 a; cvta.to.shared.u64 a, %1; cvt.u32.u64 %0, a; }"
        : "=r"(srow_a) : "l"(srow));

    if (t == 0) {
        srow[NCLASSES]        = 0.f;                 // sentinel zero slots
        srow[ROWB + NCLASSES] = 0.f;
        asm volatile("mbarrier.init.shared.b64 [%0], 1;" :: "r"(mbar_a)     : "memory");
        asm volatile("mbarrier.init.shared.b64 [%0], 1;" :: "r"(mbar_a + 8) : "memory");
    }
    __syncthreads();

    if (t == 0) {
        const float* src = x + row0 * NCLASSES;
        asm volatile("mbarrier.arrive.expect_tx.shared.b64 _, [%0], %1;"
                     :: "r"(mbar_a), "r"(NCLASSES * 4) : "memory");
        asm volatile("cp.async.bulk.shared::cta.global.mbarrier::complete_tx::bytes [%0], [%1], %2, [%3];"
                     :: "r"(srow_a), "l"(src), "r"(NCLASSES * 4), "r"(mbar_a) : "memory");
        asm volatile("mbarrier.arrive.expect_tx.shared.b64 _, [%0], %1;"
                     :: "r"(mbar_a + 8), "r"(NCLASSES * 4) : "memory");
        asm volatile("cp.async.bulk.shared::cta.global.mbarrier::complete_tx::bytes [%0], [%1], %2, [%3];"
                     :: "r"(srow_a + ROWB * 4), "l"(src + NCLASSES), "r"(NCLASSES * 4), "r"(mbar_a + 8) : "memory");
    }

    // Overlap with the copies: per-thread control data.
    const int g = t;
    const uint2* __restrict__ pp = (const uint2*)(g_perm_pad + g * PAD);
    const int iters = __ldg(&g_iters[g]);

    #define WAIT(off)                                                          \
    {   unsigned done = 0;                                                     \
        while (!done) {                                                        \
            asm volatile(                                                      \
                "{\n\t.reg .pred P;\n\t"                                       \
                "mbarrier.try_wait.parity.acquire.cta.shared::cta.b64 P, [%1], 0, 0x989680;\n\t" \
                "selp.b32 %0, 1, 0, P;\n\t}"                                   \
                : "=r"(done) : "r"(mbar_a + (off)) : "memory");                \
        }                                                                      \
    }

    // ---- row 0 ----
    WAIT(0)
    {
        float a0 = 0.f, a1 = 0.f, a2 = 0.f, a3 = 0.f;
        for (int it = 0; it < iters; ++it) {
            const uint2 v = __ldg(&pp[it]);
            a0 += srow[v.x & 0xFFFFu];
            a1 += srow[v.x >> 16];
            a2 += srow[v.y & 0xFFFFu];
            a3 += srow[v.y >> 16];
        }
        out[row0 * NGROUPS + g] = (a0 + a1) + (a2 + a3);
    }

    // ---- row 1 ----
    WAIT(8)
    {
        float b0 = 0.f, b1 = 0.f, b2 = 0.f, b3 = 0.f;
        for (int it = 0; it < iters; ++it) {
            const uint2 v = __ldg(&pp[it]);
            b0 += srow[ROWB + (v.x & 0xFFFFu)];
            b1 += srow[ROWB + (v.x >> 16)];
            b2 += srow[ROWB + (v.y & 0xFFFFu)];
            b3 += srow[ROWB + (v.y >> 16)];
        }
        out[(row0 + 1) * NGROUPS + g] = (b0 + b1) + (b2 + b3);
    }
    #undef WAIT
}

// ---------------------------------------------------------------------------
// Launch
// ---------------------------------------------------------------------------
extern "C" void kernel_launch(void* const* d_in, const int* in_sizes, int n_in,
                              void* d_out, int out_size) {
    const float* x   = (const float*)d_in[0];
    const int*   seg = (const int*)d_in[1];
    float*       out = (float*)d_out;

    const int smem_main = SMEM_FLOATS * (int)sizeof(float);   // 65792 B
    cudaFuncSetAttribute(k_main, cudaFuncAttributeMaxDynamicSharedMemorySize,
                         smem_main);

    k_perm<<<NGROUPS / 8, 256>>>(seg);
    k_main<<<BATCH / 2, 512, smem_main>>>(x, out);
}

// round 13
// speedup vs baseline: 1.2843x; 1.2843x over previous
#include <cuda_runtime.h>
#include <cuda_bf16.h>
#include <cstdint>

#define BATCH     8192
#define NCLASSES  8192
#define NGROUPS   512
#define PAD       128            // u16 slots per group (>= max group size, mult of 8)

// smem float-index layout for k_main
#define ROWB      8224           // row1 base: byte 32896 (128B aligned for TMA), bank shift 0
#define SMEM_FLOATS 16448        // row0[8192] | sent | pad | row1[8192] | sent | pad  (65792 B)

// Scratch: __device__ globals only (allocation is forbidden).
__device__ unsigned short g_perm_pad[NGROUPS * PAD]; // per-group columns (stable), sentinel = 8192
__device__ int            g_iters[NGROUPS];          // ceil(cnt/8) uint4 iterations per group

// ---------------------------------------------------------------------------
// K1: build padded, stable per-group column lists. 64 blocks x 256 threads;
// block stages seg (32KB int4) to smem, 8 warps own one group each.
// Vectorized scan: 4 columns per lane per iteration (64 iters).
// ---------------------------------------------------------------------------
__global__ __launch_bounds__(256)
void k_perm(const int* __restrict__ seg) {
    __shared__ int4 sseg4[NCLASSES / 4];
    const int t = threadIdx.x;

    const int4* s4 = (const int4*)seg;
    #pragma unroll
    for (int k = 0; k < 8; ++k)
        sseg4[t + k * 256] = s4[t + k * 256];
    __syncthreads();

    const int      lane = t & 31;
    const int      g    = blockIdx.x * 8 + (t >> 5);
    const unsigned lm   = (1u << lane) - 1u;
    unsigned short* dst = g_perm_pad + g * PAD;

    int cnt = 0;
    #pragma unroll 4
    for (int i = 0; i < 64; ++i) {
        const int4 v = sseg4[i * 32 + lane];
        const unsigned m0 = __ballot_sync(0xffffffffu, v.x == g);
        const unsigned m1 = __ballot_sync(0xffffffffu, v.y == g);
        const unsigned m2 = __ballot_sync(0xffffffffu, v.z == g);
        const unsigned m3 = __ballot_sync(0xffffffffu, v.w == g);
        const int base = (i * 32 + lane) * 4;
        const int S = __popc(m0 & lm) + __popc(m1 & lm)
                    + __popc(m2 & lm) + __popc(m3 & lm);
        const int b0 = (v.x == g), b1 = (v.y == g), b2 = (v.z == g);
        if (v.x == g) dst[cnt + S]                = (unsigned short)(base);
        if (v.y == g) dst[cnt + S + b0]           = (unsigned short)(base + 1);
        if (v.z == g) dst[cnt + S + b0 + b1]      = (unsigned short)(base + 2);
        if (v.w == g) dst[cnt + S + b0 + b1 + b2] = (unsigned short)(base + 3);
        cnt += __popc(m0) + __popc(m1) + __popc(m2) + __popc(m3);
    }
    for (int j = cnt + lane; j < PAD; j += 32)           // sentinel fill
        dst[j] = (unsigned short)NCLASSES;
    if (lane == 0) g_iters[g] = (cnt + 7) >> 3;          // uint4 (8-col) iterations
}

// ---------------------------------------------------------------------------
// K2: hot kernel (R6 structure). Two 32KB rows staged by cp.async.bulk, one
// mbarrier. Thread g gathers its group's columns: one uint4 index fetch feeds
// BOTH rows (16 LDS + 16 FADD per iter, 4 chains/row). Perm loads are
// software-pipelined: first fetch overlaps the TMA wait, subsequent fetches
// overlap the adds. Coalesced output.
// ---------------------------------------------------------------------------
__global__ __launch_bounds__(512, 3)
void k_main(const float* __restrict__ x, float* __restrict__ out) {
    extern __shared__ float srow[];                  // [0,8192) row0, [8224,16416) row1
    __shared__ __align__(8) unsigned long long mbar;

    const int t = threadIdx.x;
    const size_t row0 = (size_t)blockIdx.x * 2;

    unsigned mbar_a, srow_a;
    asm("{ .reg .u64 a; cvta.to.shared.u64 a, %1; cvt.u32.u64 %0, a; }"
        : "=r"(mbar_a) : "l"(&mbar));
    asm("{ .reg .u64 a; cvta.to.shared.u64 a, %1; cvt.u32.u64 %0, a; }"
        : "=r"(srow_a) : "l"(srow));

    if (t == 0) {
        srow[NCLASSES]        = 0.f;                 // sentinel zero slots
        srow[ROWB + NCLASSES] = 0.f;
        asm volatile("mbarrier.init.shared.b64 [%0], 1;" :: "r"(mbar_a) : "memory");
    }
    __syncthreads();

    if (t == 0) {
        asm volatile("mbarrier.arrive.expect_tx.shared.b64 _, [%0], %1;"
                     :: "r"(mbar_a), "r"(2 * NCLASSES * 4) : "memory");
        const float* src = x + row0 * NCLASSES;
        asm volatile("cp.async.bulk.shared::cta.global.mbarrier::complete_tx::bytes [%0], [%1], %2, [%3];"
                     :: "r"(srow_a), "l"(src), "r"(NCLASSES * 4), "r"(mbar_a) : "memory");
        asm volatile("cp.async.bulk.shared::cta.global.mbarrier::complete_tx::bytes [%0], [%1], %2, [%3];"
                     :: "r"(srow_a + ROWB * 4), "l"(src + NCLASSES), "r"(NCLASSES * 4), "r"(mbar_a) : "memory");
    }

    // Overlap the TMA copies: control data + first perm fetch in flight.
    const int g = t;
    const uint4* __restrict__ pp = (const uint4*)(g_perm_pad + g * PAD);
    const int iters = __ldg(&g_iters[g]);
    uint4 v = __ldg(&pp[0]);                         // always safe (sentinel-filled)

    {   // wait for both bulk copies (acquire orders TMA smem writes before LDS)
        unsigned done = 0;
        while (!done) {
            asm volatile(
                "{\n\t.reg .pred P;\n\t"
                "mbarrier.try_wait.parity.acquire.cta.shared::cta.b64 P, [%1], 0, 0x989680;\n\t"
                "selp.b32 %0, 1, 0, P;\n\t}"
                : "=r"(done) : "r"(mbar_a) : "memory");
        }
    }

    float a0 = 0.f, a1 = 0.f, a2 = 0.f, a3 = 0.f;     // row0 chains
    float b0 = 0.f, b1 = 0.f, b2 = 0.f, b3 = 0.f;     // row1 chains
    for (int it = 0; it < iters; ++it) {
        const uint4 cur = v;
        if (it + 1 < iters) v = __ldg(&pp[it + 1]);   // prefetch next indices
        unsigned idx;
        #define STEP(word, shift, A, B)                \
            idx = ((word) >> (shift)) & 0xFFFFu;       \
            A += srow[idx];                            \
            B += srow[ROWB + idx];
        STEP(cur.x,  0, a0, b0) STEP(cur.x, 16, a1, b1)
        STEP(cur.y,  0, a2, b2) STEP(cur.y, 16, a3, b3)
        STEP(cur.z,  0, a0, b0) STEP(cur.z, 16, a1, b1)
        STEP(cur.w,  0, a2, b2) STEP(cur.w, 16, a3, b3)
        #undef STEP
    }

    out[row0 * NGROUPS + g]       = (a0 + a1) + (a2 + a3);
    out[(row0 + 1) * NGROUPS + g] = (b0 + b1) + (b2 + b3);
}

// ---------------------------------------------------------------------------
// Launch
// ---------------------------------------------------------------------------
extern "C" void kernel_launch(void* const* d_in, const int* in_sizes, int n_in,
                              void* d_out, int out_size) {
    const float* x   = (const float*)d_in[0];
    const int*   seg = (const int*)d_in[1];
    float*       out = (float*)d_out;

    const int smem_main = SMEM_FLOATS * (int)sizeof(float);   // 65792 B
    cudaFuncSetAttribute(k_main, cudaFuncAttributeMaxDynamicSharedMemorySize,
                         smem_main);

    k_perm<<<NGROUPS / 8, 256>>>(seg);
    k_main<<<BATCH / 2, 512, smem_main>>>(x, out);
}

// round 14
// speedup vs baseline: 1.4522x; 1.1307x over previous
#include <cuda_runtime.h>
#include <cuda_bf16.h>
#include <cstdint>

#define BATCH     8192
#define NCLASSES  8192
#define NGROUPS   512
#define PAD       128            // u16 slots per group (>= max group size, mult of 8)

// smem float-index layout for k_main (R6 layout, measured 71.9us)
#define ROWB      8208           // row1 base (byte off 32832, 16B aligned)
#define SENT_A    8192           // zero slot for row0 sentinel reads
#define SENT_B    (ROWB + 8192)  // 16400: zero slot for row1 sentinel reads
#define SMEM_FLOATS 16416        // 65664 B -> 3 blocks/SM

// Scratch: __device__ globals only (allocation is forbidden).
__device__ unsigned short g_perm_pad[NGROUPS * PAD]; // per-group columns (stable), sentinel = 8192
__device__ int            g_iters[NGROUPS];          // ceil(cnt/8) uint4 iterations per group

// ---------------------------------------------------------------------------
// K1: build padded, stable per-group column lists. 64 blocks x 256 threads;
// block stages seg (32KB int4) to smem, 8 warps own one group each.
// Vectorized scan: 4 columns per lane per iteration (64 iters).
// ---------------------------------------------------------------------------
__global__ __launch_bounds__(256)
void k_perm(const int* __restrict__ seg) {
    __shared__ int4 sseg4[NCLASSES / 4];
    const int t = threadIdx.x;

    const int4* s4 = (const int4*)seg;
    #pragma unroll
    for (int k = 0; k < 8; ++k)
        sseg4[t + k * 256] = s4[t + k * 256];
    __syncthreads();

    const int      lane = t & 31;
    const int      g    = blockIdx.x * 8 + (t >> 5);
    const unsigned lm   = (1u << lane) - 1u;
    unsigned short* dst = g_perm_pad + g * PAD;

    int cnt = 0;
    #pragma unroll 4
    for (int i = 0; i < 64; ++i) {
        const int4 v = sseg4[i * 32 + lane];
        const unsigned m0 = __ballot_sync(0xffffffffu, v.x == g);
        const unsigned m1 = __ballot_sync(0xffffffffu, v.y == g);
        const unsigned m2 = __ballot_sync(0xffffffffu, v.z == g);
        const unsigned m3 = __ballot_sync(0xffffffffu, v.w == g);
        const int base = (i * 32 + lane) * 4;
        const int S = __popc(m0 & lm) + __popc(m1 & lm)
                    + __popc(m2 & lm) + __popc(m3 & lm);
        const int b0 = (v.x == g), b1 = (v.y == g), b2 = (v.z == g);
        if (v.x == g) dst[cnt + S]                = (unsigned short)(base);
        if (v.y == g) dst[cnt + S + b0]           = (unsigned short)(base + 1);
        if (v.z == g) dst[cnt + S + b0 + b1]      = (unsigned short)(base + 2);
        if (v.w == g) dst[cnt + S + b0 + b1 + b2] = (unsigned short)(base + 3);
        cnt += __popc(m0) + __popc(m1) + __popc(m2) + __popc(m3);
    }
    for (int j = cnt + lane; j < PAD; j += 32)           // sentinel fill
        dst[j] = (unsigned short)NCLASSES;
    if (lane == 0) g_iters[g] = (cnt + 7) >> 3;          // uint4 (8-col) iterations
}

// ---------------------------------------------------------------------------
// K2: hot kernel — exact R6 structure (measured 71.9us). Two 32KB rows staged
// by cp.async.bulk (TMA path, single thread, one mbarrier). Thread g gathers
// its group's columns: plain loop, one uint4 index fetch feeds BOTH rows
// (ptxas software-pipelines the LDG/LDS itself — do not hand-pipeline).
// ---------------------------------------------------------------------------
__global__ __launch_bounds__(512, 3)
void k_main(const float* __restrict__ x, float* __restrict__ out) {
    extern __shared__ float srow[];                  // [0,8192) row0, [8208,16400) row1
    __shared__ __align__(8) unsigned long long mbar;

    const int t = threadIdx.x;
    const size_t row0 = (size_t)blockIdx.x * 2;

    unsigned mbar_a, srow_a;
    asm("{ .reg .u64 a; cvta.to.shared.u64 a, %1; cvt.u32.u64 %0, a; }"
        : "=r"(mbar_a) : "l"(&mbar));
    asm("{ .reg .u64 a; cvta.to.shared.u64 a, %1; cvt.u32.u64 %0, a; }"
        : "=r"(srow_a) : "l"(srow));

    if (t == 0) {
        srow[SENT_A] = 0.f;                          // sentinel zero slots
        srow[SENT_B] = 0.f;
        asm volatile("mbarrier.init.shared.b64 [%0], 1;" :: "r"(mbar_a) : "memory");
    }
    __syncthreads();

    if (t == 0) {
        asm volatile("mbarrier.arrive.expect_tx.shared.b64 _, [%0], %1;"
                     :: "r"(mbar_a), "r"(2 * NCLASSES * 4) : "memory");
        const float* src = x + row0 * NCLASSES;
        asm volatile("cp.async.bulk.shared::cta.global.mbarrier::complete_tx::bytes [%0], [%1], %2, [%3];"
                     :: "r"(srow_a), "l"(src), "r"(NCLASSES * 4), "r"(mbar_a) : "memory");
        asm volatile("cp.async.bulk.shared::cta.global.mbarrier::complete_tx::bytes [%0], [%1], %2, [%3];"
                     :: "r"(srow_a + ROWB * 4), "l"(src + NCLASSES), "r"(NCLASSES * 4), "r"(mbar_a) : "memory");
    }

    // Overlap with the copy: fetch this thread's control data.
    const int g = t;
    const uint4* __restrict__ pp = (const uint4*)(g_perm_pad + g * PAD);
    const int iters = __ldg(&g_iters[g]);

    // Wait for both bulk copies (acquire orders TMA smem writes before LDS).
    {
        unsigned done = 0;
        while (!done) {
            asm volatile(
                "{\n\t.reg .pred P;\n\t"
                "mbarrier.try_wait.parity.acquire.cta.shared::cta.b64 P, [%1], 0, 0x989680;\n\t"
                "selp.b32 %0, 1, 0, P;\n\t}"
                : "=r"(done) : "r"(mbar_a) : "memory");
        }
    }

    float a0 = 0.f, a1 = 0.f, b0 = 0.f, b1 = 0.f;    // 2 chains per row
    for (int it = 0; it < iters; ++it) {
        const uint4 v = __ldg(&pp[it]);
        unsigned idx;
        #define STEP(word, shift, A, B)                \
            idx = ((word) >> (shift)) & 0xFFFFu;       \
            A += srow[idx];                            \
            B += srow[ROWB + idx];
        STEP(v.x,  0, a0, b0) STEP(v.x, 16, a1, b1)
        STEP(v.y,  0, a0, b0) STEP(v.y, 16, a1, b1)
        STEP(v.z,  0, a0, b0) STEP(v.z, 16, a1, b1)
        STEP(v.w,  0, a0, b0) STEP(v.w, 16, a1, b1)
        #undef STEP
    }

    out[row0 * NGROUPS + g]       = a0 + a1;          // coalesced: 512 floats/row
    out[(row0 + 1) * NGROUPS + g] = b0 + b1;
}

// ---------------------------------------------------------------------------
// Launch
// ---------------------------------------------------------------------------
extern "C" void kernel_launch(void* const* d_in, const int* in_sizes, int n_in,
                              void* d_out, int out_size) {
    const float* x   = (const float*)d_in[0];
    const int*   seg = (const int*)d_in[1];
    float*       out = (float*)d_out;

    const int smem_main = SMEM_FLOATS * (int)sizeof(float);   // 65664 B
    cudaFuncSetAttribute(k_main, cudaFuncAttributeMaxDynamicSharedMemorySize,
                         smem_main);

    k_perm<<<NGROUPS / 8, 256>>>(seg);
    k_main<<<BATCH / 2, 512, smem_main>>>(x, out);
}